// round 12
// baseline (speedup 1.0000x reference)
#include <cuda_runtime.h>
#include <cuda_bf16.h>
#include <cstdint>

#define TT 16384
#define DD 2048
#define EE 64
#define KSEL 8
#define BR 128
#define KCH 32
#define NCH (DD / KCH)    // 64 chunks
#define TAU 5e-5f
#define EF 40             // experts 0..39: fp32 FFMA2 pipe
#define EH 24             // experts 40..63: 3-pass bf16 HMMA

// ---- dynamic smem layout (bytes) ----
#define XFSTR 144                         // fp32 x row stride (36 floats)
#define XHSTR 80                          // bf16 x row stride
#define WHSTR 80                          // bf16 W row stride
#define XFS (BR * XFSTR)                  // 18432 per stage
#define XHS (BR * XHSTR)                  // 10240 per stage
#define WFS (KCH * 192)                   // 6144 per stage ([32][48 floats], 12/eq-group)
#define WHS (EH * WHSTR)                  // 1920 per stage
#define OFF_XF 0
#define OFF_XH (2 * XFS)                  // 36864
#define OFF_XM (OFF_XH + 2 * XHS)         // 57344
#define OFF_WF (OFF_XM + 2 * XHS)         // 77824
#define OFF_WH (OFF_WF + 2 * WFS)         // 90112
#define OFF_WM (OFF_WH + 2 * WHS)         // 93952
#define SMEM_TOTAL (OFF_WM + 2 * WHS)     // 97792

typedef unsigned long long ull;

// ---- device scratch ----
__device__ float    g_wf[NCH * KCH * 48];   // [c][dl][48]: eq-group*12 + e%10 (pad 10..11)
__device__ uint16_t g_wbh[NCH * EH * KCH];  // [c][eh][dl] bf16 hi
__device__ uint16_t g_wbm[NCH * EH * KCH];  // bf16 residual
__device__ float g_cnt[EE];
__device__ float g_pn[EE];
__device__ int   g_nflag;
__device__ int   g_frows[TT];

static __device__ __forceinline__ uint32_t s2u(const void* p) {
    uint32_t a;
    asm("{ .reg .u64 t; cvta.to.shared.u64 t, %1; cvt.u32.u64 %0, t; }" : "=r"(a) : "l"(p));
    return a;
}

#define LDSM_X4(r0, r1, r2, r3, addr) \
    asm volatile("ldmatrix.sync.aligned.m8n8.x4.shared.b16 {%0,%1,%2,%3}, [%4];" \
                 : "=r"(r0), "=r"(r1), "=r"(r2), "=r"(r3) : "r"(addr))
#define LDSM_X2(r0, r1, addr) \
    asm volatile("ldmatrix.sync.aligned.m8n8.x2.shared.b16 {%0,%1}, [%2];" \
                 : "=r"(r0), "=r"(r1) : "r"(addr))
#define MMA_BF16(c, a0, a1, a2, a3, b0, b1) \
    asm volatile("mma.sync.aligned.m16n8k16.row.col.f32.bf16.bf16.f32 " \
                 "{%0,%1,%2,%3},{%4,%5,%6,%7},{%8,%9},{%0,%1,%2,%3};" \
                 : "+f"((c)[0]), "+f"((c)[1]), "+f"((c)[2]), "+f"((c)[3]) \
                 : "r"(a0), "r"(a1), "r"(a2), "r"(a3), "r"(b0), "r"(b1))

static __device__ __forceinline__ uint32_t pack_bf16(float a, float b) {
    __nv_bfloat162 h = __floats2bfloat162_rn(a, b);
    return *(uint32_t*)&h;
}
// packed fp32x2 FMA: each 32-bit lane an independent sequential-d chain
static __device__ __forceinline__ void ffma2(ull& c, ull a, ull b) {
    asm volatile("fma.rn.f32x2 %0, %1, %2, %0;" : "+l"(c) : "l"(a), "l"(b));
}
static __device__ __forceinline__ void dup2(ull v, ull& d0, ull& d1) {
    uint32_t lo, hi;
    asm("mov.b64 {%0,%1}, %2;" : "=r"(lo), "=r"(hi) : "l"(v));
    asm("mov.b64 %0, {%1,%1};" : "=l"(d0) : "r"(lo));
    asm("mov.b64 %0, {%1,%1};" : "=l"(d1) : "r"(hi));
}

// ---------------------------------------------------------------------------
// prep: zero accumulators; split W: experts 0..39 -> padded d-major fp32,
// experts 40..63 -> bf16 hi/residual k-major, both chunked.
// ---------------------------------------------------------------------------
__global__ void prep_kernel(const float* __restrict__ W) {
    int idx = blockIdx.x * blockDim.x + threadIdx.x;
    if (idx == 0) g_nflag = 0;
    if (idx < EE)          g_cnt[idx] = 0.f;
    else if (idx < 2 * EE) g_pn[idx - EE] = 0.f;
    if (idx < DD * EE) {
        int e = idx >> 11;            // coalesced read of W[e][d]
        int d = idx & (DD - 1);
        int c = d >> 5, dl = d & 31;
        float v = W[idx];
        if (e < EF) {
            g_wf[c * (KCH * 48) + dl * 48 + (e / 10) * 12 + (e % 10)] = v;
        } else {
            __nv_bfloat16 h = __float2bfloat16(v);
            __nv_bfloat16 m = __float2bfloat16(v - __bfloat162float(h));
            int eh = e - EF;
            g_wbh[c * (EH * KCH) + eh * KCH + dl] = *(uint16_t*)&h;
            g_wbm[c * (EH * KCH) + eh * KCH + dl] = *(uint16_t*)&m;
        }
    }
}

extern __shared__ char dsm[];

// ---------------------------------------------------------------------------
// router: 128 blocks x 256 threads, 128 rows/block, dual-pipe:
// every warp runs experts 0..39 on the fp32 pipe (R7-style FFMA2 expert
// pairs, broadcast W) AND experts 40..63 on the tensor pipe (R11-proven
// 3-pass bf16 HMMA) over its 16-row tile. Margin-guarded top-8 + patch.
// ---------------------------------------------------------------------------
__global__ void __launch_bounds__(256, 1) router_kernel(
    const float* __restrict__ x,
    const float* __restrict__ bias,
    float* __restrict__ out)
{
    __shared__ float bias_s[EE];
    __shared__ float cnt_s[EE];

    const int t = threadIdx.x, wid = t >> 5, lane = t & 31;
    const int r0 = blockIdx.x * BR;
    const uint32_t sb = s2u(dsm);
    const int m0 = wid * 16;

    if (t < EE) { bias_s[t] = bias[t]; cnt_s[t] = 0.f; }

    // ---- x staging map: thread -> row t>>1, 16-float half t&1
    const int xrow = t >> 1, xh2 = t & 1;
    const float4* xg = (const float4*)(x + (size_t)(r0 + xrow) * DD + xh2 * 16);
    char* xf_st = dsm + OFF_XF + xrow * XFSTR + xh2 * 64;
    char* xh_st = dsm + OFF_XH + xrow * XHSTR + xh2 * 32;
    char* xm_st = dsm + OFF_XM + xrow * XHSTR + xh2 * 32;

    // ---- W cp.async pieces: 576 x 16B per chunk; thread does 2-3
    uint32_t pdst[3]; const char* psrc[3]; uint32_t pgst[3], psst[3];
    const int np = (t < 64) ? 3 : 2;
    #pragma unroll
    for (int i = 0; i < 3; i++) {
        int p = (i < 2) ? (t + 256 * i) : (512 + t);
        if (p < 384) {
            psrc[i] = (const char*)g_wf + p * 16;
            pdst[i] = sb + OFF_WF + p * 16;
            pgst[i] = WFS; psst[i] = WFS;
        } else if (p < 480) {
            int j = p - 384;
            psrc[i] = (const char*)g_wbh + j * 16;
            pdst[i] = sb + OFF_WH + (j >> 2) * WHSTR + (j & 3) * 16;
            pgst[i] = EH * KCH * 2; psst[i] = WHS;
        } else {
            int j = p - 480;
            psrc[i] = (const char*)g_wbm + j * 16;
            pdst[i] = sb + OFF_WM + (j >> 2) * WHSTR + (j & 3) * 16;
            pgst[i] = EH * KCH * 2; psst[i] = WHS;
        }
    }

    // ---- fp32 compute map: lane = (rq 0..7, eq 0..3); rows m0+rq, m0+rq+8;
    //      experts eq*10 .. eq*10+9 (5 FFMA2 pairs)
    const int rq = lane & 7, eq = lane >> 3;
    const char* xr0b = dsm + OFF_XF + (m0 + rq) * XFSTR;
    const char* xr1b = dsm + OFF_XF + (m0 + rq + 8) * XFSTR;
    const char* wfb  = dsm + OFF_WF + eq * 48;

    // ---- HMMA lane addresses (R11-proven)
    const uint32_t a_off  = (uint32_t)((m0 + (lane & 15)) * XHSTR + (lane >> 4) * 16);
    const uint32_t b4_off = (uint32_t)(((lane & 7) + ((lane >> 4) << 3)) * WHSTR
                                       + ((lane >> 3) & 1) * 16);
    const uint32_t b2_off = (uint32_t)((16 + (lane & 7)) * WHSTR + ((lane >> 3) & 1) * 16);

    ull  facc[2][5];
    #pragma unroll
    for (int r = 0; r < 2; r++)
        #pragma unroll
        for (int p = 0; p < 5; p++) facc[r][p] = 0ULL;
    float acc0[3][4], acc1[3][4];
    #pragma unroll
    for (int ti = 0; ti < 3; ti++)
        #pragma unroll
        for (int g = 0; g < 4; g++) { acc0[ti][g] = 0.f; acc1[ti][g] = 0.f; }

    float4 rx[4];
    #pragma unroll
    for (int j = 0; j < 4; j++) rx[j] = xg[j];

    // ---- prologue: W(0)
    #pragma unroll
    for (int i = 0; i < 3; i++)
        if (i < np)
            asm volatile("cp.async.cg.shared.global [%0], [%1], 16;"
                         :: "r"(pdst[i]), "l"(psrc[i]));
    asm volatile("cp.async.commit_group;");

    for (int c = 0; c < NCH; c++) {
        const int b = c & 1;

        // ---- stage x(c): fp32 + bf16 hi/res
        #pragma unroll
        for (int j = 0; j < 4; j++) {
            float4 v = rx[j];
            *(float4*)(xf_st + b * XFS + j * 16) = v;
            float fh0 = __bfloat162float(__float2bfloat16(v.x));
            float fh1 = __bfloat162float(__float2bfloat16(v.y));
            float fh2 = __bfloat162float(__float2bfloat16(v.z));
            float fh3 = __bfloat162float(__float2bfloat16(v.w));
            uint32_t hlo = pack_bf16(v.x, v.y), hhi = pack_bf16(v.z, v.w);
            uint32_t mlo = pack_bf16(v.x - fh0, v.y - fh1);
            uint32_t mhi = pack_bf16(v.z - fh2, v.w - fh3);
            *(ull*)(xh_st + b * XHS + j * 8) = (ull)hlo | ((ull)hhi << 32);
            *(ull*)(xm_st + b * XHS + j * 8) = (ull)mlo | ((ull)mhi << 32);
        }

        if (c + 1 < NCH) {
            // prefetch W(c+1) into other stage (it was consumed by compute(c-1))
            #pragma unroll
            for (int i = 0; i < 3; i++)
                if (i < np) {
                    uint32_t so = (b ^ 1) ? psst[i] : 0u;
                    asm volatile("cp.async.cg.shared.global [%0], [%1], 16;"
                                 :: "r"(pdst[i] + so),
                                    "l"(psrc[i] + (size_t)(c + 1) * pgst[i]));
                }
            asm volatile("cp.async.commit_group;");
            #pragma unroll
            for (int j = 0; j < 4; j++) rx[j] = xg[(size_t)(c + 1) * 8 + j];
            asm volatile("cp.async.wait_group 1;" ::: "memory");   // W(c) ready
        } else {
            asm volatile("cp.async.wait_group 0;" ::: "memory");
        }
        __syncthreads();

        // ---- tensor pipe: 2 k16 steps, 3 n-tiles, 3-pass, split accumulators
        {
            const uint32_t xho = b * XHS, xmo = b * XHS, who = b * WHS;
            #pragma unroll
            for (int ks = 0; ks < 2; ks++) {
                uint32_t ah0, ah1, ah2r, ah3, am0, am1, am2, am3;
                LDSM_X4(ah0, ah1, ah2r, ah3, sb + OFF_XH + xho + a_off + ks * 32);
                LDSM_X4(am0, am1, am2, am3, sb + OFF_XM + xmo + a_off + ks * 32);
                uint32_t bh0, bh1, bh2, bh3, bm0, bm1, bm2, bm3, ch0, ch1, cm0, cm1;
                LDSM_X4(bh0, bh1, bh2, bh3, sb + OFF_WH + who + b4_off + ks * 32);
                LDSM_X4(bm0, bm1, bm2, bm3, sb + OFF_WM + who + b4_off + ks * 32);
                LDSM_X2(ch0, ch1, sb + OFF_WH + who + b2_off + ks * 32);
                LDSM_X2(cm0, cm1, sb + OFF_WM + who + b2_off + ks * 32);
                // hh -> acc0
                MMA_BF16(acc0[0], ah0, ah1, ah2r, ah3, bh0, bh1);
                MMA_BF16(acc0[1], ah0, ah1, ah2r, ah3, bh2, bh3);
                MMA_BF16(acc0[2], ah0, ah1, ah2r, ah3, ch0, ch1);
                // hm -> acc1
                MMA_BF16(acc1[0], ah0, ah1, ah2r, ah3, bm0, bm1);
                MMA_BF16(acc1[1], ah0, ah1, ah2r, ah3, bm2, bm3);
                MMA_BF16(acc1[2], ah0, ah1, ah2r, ah3, cm0, cm1);
                // mh -> acc1 (3 apart from same-acc writes)
                MMA_BF16(acc1[0], am0, am1, am2, am3, bh0, bh1);
                MMA_BF16(acc1[1], am0, am1, am2, am3, bh2, bh3);
                MMA_BF16(acc1[2], am0, am1, am2, am3, ch0, ch1);
            }
        }

        // ---- fp32 pipe: 5 expert-pairs x 2 rows, sequential-d FFMA2 chains
        {
            const char* xr0 = xr0b + b * XFS;
            const char* xr1 = xr1b + b * XFS;
            const char* wf  = wfb + b * WFS;
            #pragma unroll
            for (int dl = 0; dl < KCH; dl += 2) {
                ull xa = *(const ull*)(xr0 + dl * 4);
                ull xb = *(const ull*)(xr1 + dl * 4);
                ulonglong2 w0a = *(const ulonglong2*)(wf + dl * 192);
                ulonglong2 w0b = *(const ulonglong2*)(wf + dl * 192 + 16);
                ull        w0c = *(const ull*)(wf + dl * 192 + 32);
                ulonglong2 w1a = *(const ulonglong2*)(wf + (dl + 1) * 192);
                ulonglong2 w1b = *(const ulonglong2*)(wf + (dl + 1) * 192 + 16);
                ull        w1c = *(const ull*)(wf + (dl + 1) * 192 + 32);
                ull a0, a1, b0, b1;
                dup2(xa, a0, a1);
                dup2(xb, b0, b1);
                // d = dl (10 independent accs)
                ffma2(facc[0][0], a0, w0a.x); ffma2(facc[0][1], a0, w0a.y);
                ffma2(facc[0][2], a0, w0b.x); ffma2(facc[0][3], a0, w0b.y);
                ffma2(facc[0][4], a0, w0c);
                ffma2(facc[1][0], b0, w0a.x); ffma2(facc[1][1], b0, w0a.y);
                ffma2(facc[1][2], b0, w0b.x); ffma2(facc[1][3], b0, w0b.y);
                ffma2(facc[1][4], b0, w0c);
                // d = dl+1
                ffma2(facc[0][0], a1, w1a.x); ffma2(facc[0][1], a1, w1a.y);
                ffma2(facc[0][2], a1, w1b.x); ffma2(facc[0][3], a1, w1b.y);
                ffma2(facc[0][4], a1, w1c);
                ffma2(facc[1][0], b1, w1a.x); ffma2(facc[1][1], b1, w1a.y);
                ffma2(facc[1][2], b1, w1b.x); ffma2(facc[1][3], b1, w1b.y);
                ffma2(facc[1][4], b1, w1c);
            }
        }
        __syncthreads();   // compute(c) done before stage reuse
    }

    // ---- logits -> L[128][68] overlay (on dead XF region)
    float* Lf = (float*)dsm;
    {
        #pragma unroll
        for (int r = 0; r < 2; r++) {
            const int row = m0 + rq + 8 * r;
            #pragma unroll
            for (int p = 0; p < 5; p++) {
                float2 f = *(float2*)&facc[r][p];
                const int e = eq * 10 + 2 * p;
                Lf[row * 68 + e]     = f.x;
                Lf[row * 68 + e + 1] = f.y;
            }
        }
        const int rr = m0 + (lane >> 2);
        const int cc = (lane & 3) * 2;
        #pragma unroll
        for (int ti = 0; ti < 3; ti++) {
            const int n0 = EF + ti * 8 + cc;
            Lf[rr * 68 + n0]           = acc0[ti][0] + acc1[ti][0];
            Lf[rr * 68 + n0 + 1]       = acc0[ti][1] + acc1[ti][1];
            Lf[(rr + 8) * 68 + n0]     = acc0[ti][2] + acc1[ti][2];
            Lf[(rr + 8) * 68 + n0 + 1] = acc0[ti][3] + acc1[ti][3];
        }
    }
    __syncthreads();

    // ---- per-row: sigmoid, top-9 margin test, finalize or flag
    if (t < BR) {
        float* Lr = Lf + t * 68;
        float ssum = 0.f;
        #pragma unroll
        for (int e = 0; e < EE; e++) {
            float a = 1.f / (1.f + expf(-Lr[e]));
            Lr[e] = a; ssum += a;
        }
        ull mask = 0ULL;
        float v9[9]; int i9[9];
        #pragma unroll
        for (int k = 0; k < 9; k++) {
            float best = -3.4e38f; int bi = 0;
            for (int e = 0; e < EE; e++) {
                if ((mask >> e) & 1ULL) continue;
                float v = Lr[e] + bias_s[e];
                if (v > best) { best = v; bi = e; }
            }
            mask |= 1ULL << bi; v9[k] = best; i9[k] = bi;
        }
        float ming = 3.4e38f;
        #pragma unroll
        for (int k = 0; k < 8; k++) ming = fminf(ming, v9[k] - v9[k + 1]);
        if (ming < TAU) {
            int s = atomicAdd(&g_nflag, 1);
            g_frows[s] = r0 + t;
            #pragma unroll
            for (int e = 0; e < EE; e++) Lr[e] = 0.f;   // exclude from P partials
        } else {
            float gsum = 0.f; float gv[KSEL];
            #pragma unroll
            for (int k = 0; k < KSEL; k++) {
                gv[k] = Lr[i9[k]]; gsum += gv[k];
                atomicAdd(&cnt_s[i9[k]], 1.f);
            }
            float inv = 1.f / (gsum + 1e-9f);
            size_t rg = (size_t)(r0 + t);
            #pragma unroll
            for (int k = 0; k < KSEL; k++) {
                out[rg * KSEL + k]                     = gv[k] * inv;
                out[(size_t)TT * KSEL + rg * KSEL + k] = (float)i9[k];
            }
            float pinv = 1.f / (ssum + 1e-9f);
            #pragma unroll
            for (int e = 0; e < EE; e++) Lr[e] *= pinv;
        }
    }
    __syncthreads();

    // ---- per-expert partial sums of affinity_norm
    {
        const int e = t & 63, seg = t >> 6;
        float s = 0.f;
        #pragma unroll
        for (int r = seg * 32; r < seg * 32 + 32; r++) s += Lf[r * 68 + e];
        atomicAdd(&g_pn[e], s);
    }
    if (t < EE) atomicAdd(&g_cnt[t], cnt_s[t]);
}

// ---------------------------------------------------------------------------
// patch: exact sequential-d fp32 recompute (R5/R7 numerics) for flagged rows
// ---------------------------------------------------------------------------
__global__ void __launch_bounds__(64) patch_kernel(
    const float* __restrict__ x, const float* __restrict__ W,
    const float* __restrict__ bias, float* __restrict__ out)
{
    __shared__ float xs[DD];
    __shared__ float aff[EE];
    __shared__ float pinv_s;
    const int e = threadIdx.x;
    const int nf = g_nflag;
    for (int i = blockIdx.x; i < nf; i += gridDim.x) {
        const int r = g_frows[i];
        for (int q = e; q < DD / 4; q += 64)
            ((float4*)xs)[q] = ((const float4*)(x + (size_t)r * DD))[q];
        __syncthreads();
        const float4* wr = (const float4*)(W + (size_t)e * DD);
        float acc = 0.f;
        #pragma unroll 4
        for (int q = 0; q < DD / 4; q++) {
            float4 w = wr[q];
            acc = fmaf(xs[4 * q + 0], w.x, acc);
            acc = fmaf(xs[4 * q + 1], w.y, acc);
            acc = fmaf(xs[4 * q + 2], w.z, acc);
            acc = fmaf(xs[4 * q + 3], w.w, acc);
        }
        aff[e] = 1.f / (1.f + expf(-acc));
        __syncthreads();
        if (e == 0) {
            float ssum = 0.f;
            for (int k = 0; k < EE; k++) ssum += aff[k];
            ull mask = 0ULL; float gsum = 0.f;
            float gv[KSEL]; int gi[KSEL];
            for (int k = 0; k < KSEL; k++) {
                float best = -3.4e38f; int bi = 0;
                for (int j = 0; j < EE; j++) {
                    if ((mask >> j) & 1ULL) continue;
                    float v = aff[j] + bias[j];
                    if (v > best) { best = v; bi = j; }
                }
                mask |= 1ULL << bi; gi[k] = bi;
                float a = aff[bi]; gv[k] = a; gsum += a;
                atomicAdd(&g_cnt[bi], 1.f);
            }
            float inv = 1.f / (gsum + 1e-9f);
            for (int k = 0; k < KSEL; k++) {
                out[(size_t)r * KSEL + k]                     = gv[k] * inv;
                out[(size_t)TT * KSEL + (size_t)r * KSEL + k] = (float)gi[k];
            }
            pinv_s = 1.f / (ssum + 1e-9f);
        }
        __syncthreads();
        atomicAdd(&g_pn[e], aff[e] * pinv_s);
        __syncthreads();
    }
}

// ---------------------------------------------------------------------------
__global__ void finalize_kernel(float* __restrict__ out) {
    __shared__ float red[EE];
    const int e = threadIdx.x;
    red[e] = g_cnt[e] * g_pn[e];
    __syncthreads();
    if (e == 0) {
        float s = 0.f;
        for (int i = 0; i < EE; i++) s += red[i];
        double loss = (double)s * 1e-4 * 64.0 / (8.0 * 16384.0) / 16384.0;
        out[(size_t)2 * TT * KSEL] = (float)loss;
    }
}

// ---------------------------------------------------------------------------
extern "C" void kernel_launch(void* const* d_in, const int* in_sizes, int n_in,
                              void* d_out, int out_size) {
    const float* x    = (const float*)d_in[0];
    const float* W    = (const float*)d_in[1];
    const float* bias = (const float*)d_in[2];
    float* out = (float*)d_out;

    static bool attr_done = false;
    if (!attr_done) {
        cudaFuncSetAttribute(router_kernel,
                             cudaFuncAttributeMaxDynamicSharedMemorySize, SMEM_TOTAL);
        attr_done = true;
    }

    prep_kernel<<<512, 256>>>(W);
    router_kernel<<<TT / BR, 256, SMEM_TOTAL>>>(x, bias, out);
    patch_kernel<<<512, 64>>>(x, W, bias, out);
    finalize_kernel<<<1, 64>>>(out);
}

// round 13
// speedup vs baseline: 1.0504x; 1.0504x over previous
#include <cuda_runtime.h>
#include <cuda_bf16.h>
#include <cstdint>

#define TT 16384
#define DD 2048
#define EE 64
#define KSEL 8
#define BR 128
#define KCH 32
#define NCH (DD / KCH)    // 64 chunks
#define TAU 5e-5f
#define EF 40             // experts 0..39: fp32 FFMA2 warps
#define EH 24             // experts 40..63: 3-pass bf16 HMMA warps
#define NT 512            // 16 warps: 0..7 fp32, 8..15 HMMA

// ---- dynamic smem layout (bytes) ----
#define XFSTR 144                         // fp32 x row stride (36 floats)
#define XHSTR 80                          // bf16 x row stride
#define WHSTR 80                          // bf16 W row stride
#define XFS (BR * XFSTR)                  // 18432 per stage
#define XHS (BR * XHSTR)                  // 10240 per stage
#define WFS (KCH * 192)                   // 6144 per stage ([32][48 floats])
#define WHS (EH * WHSTR)                  // 1920 per stage
#define OFF_XF 0
#define OFF_XH (2 * XFS)                  // 36864
#define OFF_XM (OFF_XH + 2 * XHS)         // 57344
#define OFF_WF (OFF_XM + 2 * XHS)         // 77824
#define OFF_WH (OFF_WF + 2 * WFS)         // 90112
#define OFF_WM (OFF_WH + 2 * WHS)         // 93952
#define SMEM_TOTAL (OFF_WM + 2 * WHS)     // 97792

typedef unsigned long long ull;

// ---- device scratch ----
__device__ float    g_wf[NCH * KCH * 48];   // [c][dl][48]: eq*12 + e%10 (pad 10..11)
__device__ uint16_t g_wbh[NCH * EH * KCH];  // [c][eh][dl] bf16 hi
__device__ uint16_t g_wbm[NCH * EH * KCH];  // bf16 residual
__device__ float g_cnt[EE];
__device__ float g_pn[EE];
__device__ int   g_nflag;
__device__ int   g_frows[TT];

static __device__ __forceinline__ uint32_t s2u(const void* p) {
    uint32_t a;
    asm("{ .reg .u64 t; cvta.to.shared.u64 t, %1; cvt.u32.u64 %0, t; }" : "=r"(a) : "l"(p));
    return a;
}

#define LDSM_X4(r0, r1, r2, r3, addr) \
    asm volatile("ldmatrix.sync.aligned.m8n8.x4.shared.b16 {%0,%1,%2,%3}, [%4];" \
                 : "=r"(r0), "=r"(r1), "=r"(r2), "=r"(r3) : "r"(addr))
#define LDSM_X2(r0, r1, addr) \
    asm volatile("ldmatrix.sync.aligned.m8n8.x2.shared.b16 {%0,%1}, [%2];" \
                 : "=r"(r0), "=r"(r1) : "r"(addr))
#define MMA_BF16(c, a0, a1, a2, a3, b0, b1) \
    asm volatile("mma.sync.aligned.m16n8k16.row.col.f32.bf16.bf16.f32 " \
                 "{%0,%1,%2,%3},{%4,%5,%6,%7},{%8,%9},{%0,%1,%2,%3};" \
                 : "+f"((c)[0]), "+f"((c)[1]), "+f"((c)[2]), "+f"((c)[3]) \
                 : "r"(a0), "r"(a1), "r"(a2), "r"(a3), "r"(b0), "r"(b1))

static __device__ __forceinline__ uint32_t pack_bf16(float a, float b) {
    __nv_bfloat162 h = __floats2bfloat162_rn(a, b);
    return *(uint32_t*)&h;
}
static __device__ __forceinline__ void ffma2(ull& c, ull a, ull b) {
    asm volatile("fma.rn.f32x2 %0, %1, %2, %0;" : "+l"(c) : "l"(a), "l"(b));
}
static __device__ __forceinline__ void dup2(ull v, ull& d0, ull& d1) {
    uint32_t lo, hi;
    asm("mov.b64 {%0,%1}, %2;" : "=r"(lo), "=r"(hi) : "l"(v));
    asm("mov.b64 %0, {%1,%1};" : "=l"(d0) : "r"(lo));
    asm("mov.b64 %0, {%1,%1};" : "=l"(d1) : "r"(hi));
}

// ---------------------------------------------------------------------------
// prep (identical to R12 — proven)
// ---------------------------------------------------------------------------
__global__ void prep_kernel(const float* __restrict__ W) {
    int idx = blockIdx.x * blockDim.x + threadIdx.x;
    if (idx == 0) g_nflag = 0;
    if (idx < EE)          g_cnt[idx] = 0.f;
    else if (idx < 2 * EE) g_pn[idx - EE] = 0.f;
    if (idx < DD * EE) {
        int e = idx >> 11;
        int d = idx & (DD - 1);
        int c = d >> 5, dl = d & 31;
        float v = W[idx];
        if (e < EF) {
            g_wf[c * (KCH * 48) + dl * 48 + (e / 10) * 12 + (e % 10)] = v;
        } else {
            __nv_bfloat16 h = __float2bfloat16(v);
            __nv_bfloat16 m = __float2bfloat16(v - __bfloat162float(h));
            int eh = e - EF;
            g_wbh[c * (EH * KCH) + eh * KCH + dl] = *(uint16_t*)&h;
            g_wbm[c * (EH * KCH) + eh * KCH + dl] = *(uint16_t*)&m;
        }
    }
}

extern __shared__ char dsm[];

// ---------------------------------------------------------------------------
// router: 128 blocks x 512 threads (16 warps), 128 rows/block.
// WARP-SPECIALIZED dual pipe: warps 0..7 = fp32 FFMA2 (experts 0..39, exact
// sequential-d chains, R12-proven math); warps 8..15 = 3-pass bf16 HMMA
// (experts 40..63, R11/R12-proven fragments). Each SMSP holds 2 of each kind
// so both pipes run concurrently without per-warp instruction mixing.
// ---------------------------------------------------------------------------
__global__ void __launch_bounds__(NT, 1) router_kernel(
    const float* __restrict__ x,
    const float* __restrict__ bias,
    float* __restrict__ out)
{
    __shared__ float bias_s[EE];
    __shared__ float cnt_s[EE];

    const int t = threadIdx.x, wid = t >> 5, lane = t & 31;
    const int r0 = blockIdx.x * BR;
    const uint32_t sb = s2u(dsm);

    if (t < EE) { bias_s[t] = bias[t]; cnt_s[t] = 0.f; }

    // ---- x staging: thread -> row t>>2, 8-float quarter t&3
    const int xrow = t >> 2, xq = t & 3;
    const float4* xgf4 = (const float4*)(x + (size_t)(r0 + xrow) * DD) + 2 * xq;
    char* xf_st = dsm + OFF_XF + xrow * XFSTR + xq * 32;
    char* xh_st = dsm + OFF_XH + xrow * XHSTR + xq * 16;
    char* xm_st = dsm + OFF_XM + xrow * XHSTR + xq * 16;

    // ---- W cp.async: 576 x 16B pieces per chunk; thread t does piece t,
    //      threads 0..63 also piece 512+t
    uint32_t pdst[2]; const char* psrc[2]; uint32_t pgst[2], psst[2];
    const int np = (t < 64) ? 2 : 1;
    #pragma unroll
    for (int i = 0; i < 2; i++) {
        int p = (i == 0) ? t : (512 + t);
        if (p < 384) {
            psrc[i] = (const char*)g_wf + p * 16;
            pdst[i] = sb + OFF_WF + p * 16;
            pgst[i] = WFS; psst[i] = WFS;
        } else if (p < 480) {
            int j = p - 384;
            psrc[i] = (const char*)g_wbh + j * 16;
            pdst[i] = sb + OFF_WH + (j >> 2) * WHSTR + (j & 3) * 16;
            pgst[i] = EH * KCH * 2; psst[i] = WHS;
        } else {
            int j = p - 480;
            psrc[i] = (const char*)g_wbm + j * 16;
            pdst[i] = sb + OFF_WM + (j >> 2) * WHSTR + (j & 3) * 16;
            pgst[i] = EH * KCH * 2; psst[i] = WHS;
        }
    }

    // ---- fp32 warp mapping (wid 0..7): tile rows m0f..m0f+15
    const int m0f = wid * 16;
    const int rq = lane & 7, eq = lane >> 3;
    const char* xr0b = dsm + OFF_XF + (m0f + rq) * XFSTR;
    const char* xr1b = dsm + OFF_XF + (m0f + rq + 8) * XFSTR;
    const char* wfb  = dsm + OFF_WF + eq * 48;

    // ---- HMMA warp mapping (wid 8..15): tile rows m0h..m0h+15
    const int m0h = (wid - 8) * 16;
    const uint32_t a_off  = (uint32_t)((m0h + (lane & 15)) * XHSTR + (lane >> 4) * 16);
    const uint32_t b4_off = (uint32_t)(((lane & 7) + ((lane >> 4) << 3)) * WHSTR
                                       + ((lane >> 3) & 1) * 16);
    const uint32_t b2_off = (uint32_t)((16 + (lane & 7)) * WHSTR + ((lane >> 3) & 1) * 16);

    ull  facc[2][5];
    #pragma unroll
    for (int r = 0; r < 2; r++)
        #pragma unroll
        for (int p = 0; p < 5; p++) facc[r][p] = 0ULL;
    float acc0[3][4], acc1[3][4];
    #pragma unroll
    for (int ti = 0; ti < 3; ti++)
        #pragma unroll
        for (int g = 0; g < 4; g++) { acc0[ti][g] = 0.f; acc1[ti][g] = 0.f; }

    float4 rx0 = xgf4[0], rx1 = xgf4[1];

    // ---- prologue: W(0)
    #pragma unroll
    for (int i = 0; i < 2; i++)
        if (i < np)
            asm volatile("cp.async.cg.shared.global [%0], [%1], 16;"
                         :: "r"(pdst[i]), "l"(psrc[i]));
    asm volatile("cp.async.commit_group;");

    for (int c = 0; c < NCH; c++) {
        const int b = c & 1;

        // ---- stage x(c): fp32 copy + bf16 hi/res split (all threads)
        {
            *(float4*)(xf_st + b * XFS)      = rx0;
            *(float4*)(xf_st + b * XFS + 16) = rx1;
            float h0 = __bfloat162float(__float2bfloat16(rx0.x));
            float h1 = __bfloat162float(__float2bfloat16(rx0.y));
            float h2 = __bfloat162float(__float2bfloat16(rx0.z));
            float h3 = __bfloat162float(__float2bfloat16(rx0.w));
            float h4 = __bfloat162float(__float2bfloat16(rx1.x));
            float h5 = __bfloat162float(__float2bfloat16(rx1.y));
            float h6 = __bfloat162float(__float2bfloat16(rx1.z));
            float h7 = __bfloat162float(__float2bfloat16(rx1.w));
            uint4 hv = { pack_bf16(rx0.x, rx0.y), pack_bf16(rx0.z, rx0.w),
                         pack_bf16(rx1.x, rx1.y), pack_bf16(rx1.z, rx1.w) };
            uint4 mv = { pack_bf16(rx0.x - h0, rx0.y - h1),
                         pack_bf16(rx0.z - h2, rx0.w - h3),
                         pack_bf16(rx1.x - h4, rx1.y - h5),
                         pack_bf16(rx1.z - h6, rx1.w - h7) };
            *(uint4*)(xh_st + b * XHS) = hv;
            *(uint4*)(xm_st + b * XHS) = mv;
        }

        if (c + 1 < NCH) {
            #pragma unroll
            for (int i = 0; i < 2; i++)
                if (i < np) {
                    uint32_t so = (b ^ 1) ? psst[i] : 0u;
                    asm volatile("cp.async.cg.shared.global [%0], [%1], 16;"
                                 :: "r"(pdst[i] + so),
                                    "l"(psrc[i] + (size_t)(c + 1) * pgst[i]));
                }
            asm volatile("cp.async.commit_group;");
            rx0 = xgf4[(size_t)(c + 1) * 8];
            rx1 = xgf4[(size_t)(c + 1) * 8 + 1];
            asm volatile("cp.async.wait_group 1;" ::: "memory");
        } else {
            asm volatile("cp.async.wait_group 0;" ::: "memory");
        }
        __syncthreads();

        if (wid < 8) {
            // ---- fp32 warps: 5 expert-pairs x 2 rows, sequential-d FFMA2
            const char* xr0 = xr0b + b * XFS;
            const char* xr1 = xr1b + b * XFS;
            const char* wf  = wfb + b * WFS;
            #pragma unroll
            for (int dl = 0; dl < KCH; dl += 2) {
                ull xa = *(const ull*)(xr0 + dl * 4);
                ull xb = *(const ull*)(xr1 + dl * 4);
                ulonglong2 w0a = *(const ulonglong2*)(wf + dl * 192);
                ulonglong2 w0b = *(const ulonglong2*)(wf + dl * 192 + 16);
                ull        w0c = *(const ull*)(wf + dl * 192 + 32);
                ulonglong2 w1a = *(const ulonglong2*)(wf + (dl + 1) * 192);
                ulonglong2 w1b = *(const ulonglong2*)(wf + (dl + 1) * 192 + 16);
                ull        w1c = *(const ull*)(wf + (dl + 1) * 192 + 32);
                ull a0, a1, b0, b1;
                dup2(xa, a0, a1);
                dup2(xb, b0, b1);
                ffma2(facc[0][0], a0, w0a.x); ffma2(facc[0][1], a0, w0a.y);
                ffma2(facc[0][2], a0, w0b.x); ffma2(facc[0][3], a0, w0b.y);
                ffma2(facc[0][4], a0, w0c);
                ffma2(facc[1][0], b0, w0a.x); ffma2(facc[1][1], b0, w0a.y);
                ffma2(facc[1][2], b0, w0b.x); ffma2(facc[1][3], b0, w0b.y);
                ffma2(facc[1][4], b0, w0c);
                ffma2(facc[0][0], a1, w1a.x); ffma2(facc[0][1], a1, w1a.y);
                ffma2(facc[0][2], a1, w1b.x); ffma2(facc[0][3], a1, w1b.y);
                ffma2(facc[0][4], a1, w1c);
                ffma2(facc[1][0], b1, w1a.x); ffma2(facc[1][1], b1, w1a.y);
                ffma2(facc[1][2], b1, w1b.x); ffma2(facc[1][3], b1, w1b.y);
                ffma2(facc[1][4], b1, w1c);
            }
        } else {
            // ---- HMMA warps: 2 k16 steps, 3 n-tiles, 3-pass, split accs
            const uint32_t xho = b * XHS, who = b * WHS;
            #pragma unroll
            for (int ks = 0; ks < 2; ks++) {
                uint32_t ah0, ah1, ah2r, ah3, am0, am1, am2, am3;
                LDSM_X4(ah0, ah1, ah2r, ah3, sb + OFF_XH + xho + a_off + ks * 32);
                LDSM_X4(am0, am1, am2, am3, sb + OFF_XM + xho + a_off + ks * 32);
                uint32_t bh0, bh1, bh2, bh3, bm0, bm1, bm2, bm3, ch0, ch1, cm0, cm1;
                LDSM_X4(bh0, bh1, bh2, bh3, sb + OFF_WH + who + b4_off + ks * 32);
                LDSM_X4(bm0, bm1, bm2, bm3, sb + OFF_WM + who + b4_off + ks * 32);
                LDSM_X2(ch0, ch1, sb + OFF_WH + who + b2_off + ks * 32);
                LDSM_X2(cm0, cm1, sb + OFF_WM + who + b2_off + ks * 32);
                MMA_BF16(acc0[0], ah0, ah1, ah2r, ah3, bh0, bh1);
                MMA_BF16(acc0[1], ah0, ah1, ah2r, ah3, bh2, bh3);
                MMA_BF16(acc0[2], ah0, ah1, ah2r, ah3, ch0, ch1);
                MMA_BF16(acc1[0], ah0, ah1, ah2r, ah3, bm0, bm1);
                MMA_BF16(acc1[1], ah0, ah1, ah2r, ah3, bm2, bm3);
                MMA_BF16(acc1[2], ah0, ah1, ah2r, ah3, cm0, cm1);
                MMA_BF16(acc1[0], am0, am1, am2, am3, bh0, bh1);
                MMA_BF16(acc1[1], am0, am1, am2, am3, bh2, bh3);
                MMA_BF16(acc1[2], am0, am1, am2, am3, ch0, ch1);
            }
        }
        __syncthreads();
    }

    // ---- logits -> L[128][68] overlay (dead XF region)
    float* Lf = (float*)dsm;
    if (wid < 8) {
        #pragma unroll
        for (int r = 0; r < 2; r++) {
            const int row = m0f + rq + 8 * r;
            #pragma unroll
            for (int p = 0; p < 5; p++) {
                float2 f = *(float2*)&facc[r][p];
                const int e = eq * 10 + 2 * p;
                Lf[row * 68 + e]     = f.x;
                Lf[row * 68 + e + 1] = f.y;
            }
        }
    } else {
        const int rr = m0h + (lane >> 2);
        const int cc = (lane & 3) * 2;
        #pragma unroll
        for (int ti = 0; ti < 3; ti++) {
            const int n0 = EF + ti * 8 + cc;
            Lf[rr * 68 + n0]           = acc0[ti][0] + acc1[ti][0];
            Lf[rr * 68 + n0 + 1]       = acc0[ti][1] + acc1[ti][1];
            Lf[(rr + 8) * 68 + n0]     = acc0[ti][2] + acc1[ti][2];
            Lf[(rr + 8) * 68 + n0 + 1] = acc0[ti][3] + acc1[ti][3];
        }
    }
    __syncthreads();

    // ---- per-row: sigmoid, top-9 margin test, finalize or flag
    if (t < BR) {
        float* Lr = Lf + t * 68;
        float ssum = 0.f;
        #pragma unroll
        for (int e = 0; e < EE; e++) {
            float a = 1.f / (1.f + expf(-Lr[e]));
            Lr[e] = a; ssum += a;
        }
        ull mask = 0ULL;
        float v9[9]; int i9[9];
        #pragma unroll
        for (int k = 0; k < 9; k++) {
            float best = -3.4e38f; int bi = 0;
            for (int e = 0; e < EE; e++) {
                if ((mask >> e) & 1ULL) continue;
                float v = Lr[e] + bias_s[e];
                if (v > best) { best = v; bi = e; }
            }
            mask |= 1ULL << bi; v9[k] = best; i9[k] = bi;
        }
        float ming = 3.4e38f;
        #pragma unroll
        for (int k = 0; k < 8; k++) ming = fminf(ming, v9[k] - v9[k + 1]);
        if (ming < TAU) {
            int s = atomicAdd(&g_nflag, 1);
            g_frows[s] = r0 + t;
            #pragma unroll
            for (int e = 0; e < EE; e++) Lr[e] = 0.f;
        } else {
            float gsum = 0.f; float gv[KSEL];
            #pragma unroll
            for (int k = 0; k < KSEL; k++) {
                gv[k] = Lr[i9[k]]; gsum += gv[k];
                atomicAdd(&cnt_s[i9[k]], 1.f);
            }
            float inv = 1.f / (gsum + 1e-9f);
            size_t rg = (size_t)(r0 + t);
            #pragma unroll
            for (int k = 0; k < KSEL; k++) {
                out[rg * KSEL + k]                     = gv[k] * inv;
                out[(size_t)TT * KSEL + rg * KSEL + k] = (float)i9[k];
            }
            float pinv = 1.f / (ssum + 1e-9f);
            #pragma unroll
            for (int e = 0; e < EE; e++) Lr[e] *= pinv;
        }
    }
    __syncthreads();

    // ---- per-expert partial sums of affinity_norm (512 threads: 8 segs x 16)
    {
        const int e = t & 63, seg = t >> 6;
        float s = 0.f;
        #pragma unroll
        for (int r = seg * 16; r < seg * 16 + 16; r++) s += Lf[r * 68 + e];
        atomicAdd(&g_pn[e], s);
    }
    if (t < EE) atomicAdd(&g_cnt[t], cnt_s[t]);
}

// ---------------------------------------------------------------------------
// patch: exact sequential-d fp32 recompute (R5/R7 numerics) for flagged rows
// ---------------------------------------------------------------------------
__global__ void __launch_bounds__(64) patch_kernel(
    const float* __restrict__ x, const float* __restrict__ W,
    const float* __restrict__ bias, float* __restrict__ out)
{
    __shared__ float xs[DD];
    __shared__ float aff[EE];
    __shared__ float pinv_s;
    const int e = threadIdx.x;
    const int nf = g_nflag;
    for (int i = blockIdx.x; i < nf; i += gridDim.x) {
        const int r = g_frows[i];
        for (int q = e; q < DD / 4; q += 64)
            ((float4*)xs)[q] = ((const float4*)(x + (size_t)r * DD))[q];
        __syncthreads();
        const float4* wr = (const float4*)(W + (size_t)e * DD);
        float acc = 0.f;
        #pragma unroll 4
        for (int q = 0; q < DD / 4; q++) {
            float4 w = wr[q];
            acc = fmaf(xs[4 * q + 0], w.x, acc);
            acc = fmaf(xs[4 * q + 1], w.y, acc);
            acc = fmaf(xs[4 * q + 2], w.z, acc);
            acc = fmaf(xs[4 * q + 3], w.w, acc);
        }
        aff[e] = 1.f / (1.f + expf(-acc));
        __syncthreads();
        if (e == 0) {
            float ssum = 0.f;
            for (int k = 0; k < EE; k++) ssum += aff[k];
            ull mask = 0ULL; float gsum = 0.f;
            float gv[KSEL]; int gi[KSEL];
            for (int k = 0; k < KSEL; k++) {
                float best = -3.4e38f; int bi = 0;
                for (int j = 0; j < EE; j++) {
                    if ((mask >> j) & 1ULL) continue;
                    float v = aff[j] + bias[j];
                    if (v > best) { best = v; bi = j; }
                }
                mask |= 1ULL << bi; gi[k] = bi;
                float a = aff[bi]; gv[k] = a; gsum += a;
                atomicAdd(&g_cnt[bi], 1.f);
            }
            float inv = 1.f / (gsum + 1e-9f);
            for (int k = 0; k < KSEL; k++) {
                out[(size_t)r * KSEL + k]                     = gv[k] * inv;
                out[(size_t)TT * KSEL + (size_t)r * KSEL + k] = (float)gi[k];
            }
            pinv_s = 1.f / (ssum + 1e-9f);
        }
        __syncthreads();
        atomicAdd(&g_pn[e], aff[e] * pinv_s);
        __syncthreads();
    }
}

// ---------------------------------------------------------------------------
__global__ void finalize_kernel(float* __restrict__ out) {
    __shared__ float red[EE];
    const int e = threadIdx.x;
    red[e] = g_cnt[e] * g_pn[e];
    __syncthreads();
    if (e == 0) {
        float s = 0.f;
        for (int i = 0; i < EE; i++) s += red[i];
        double loss = (double)s * 1e-4 * 64.0 / (8.0 * 16384.0) / 16384.0;
        out[(size_t)2 * TT * KSEL] = (float)loss;
    }
}

// ---------------------------------------------------------------------------
extern "C" void kernel_launch(void* const* d_in, const int* in_sizes, int n_in,
                              void* d_out, int out_size) {
    const float* x    = (const float*)d_in[0];
    const float* W    = (const float*)d_in[1];
    const float* bias = (const float*)d_in[2];
    float* out = (float*)d_out;

    static bool attr_done = false;
    if (!attr_done) {
        cudaFuncSetAttribute(router_kernel,
                             cudaFuncAttributeMaxDynamicSharedMemorySize, SMEM_TOTAL);
        attr_done = true;
    }

    prep_kernel<<<512, 256>>>(W);
    router_kernel<<<TT / BR, NT, SMEM_TOTAL>>>(x, bias, out);
    patch_kernel<<<512, 64>>>(x, W, bias, out);
    finalize_kernel<<<1, 64>>>(out);
}

// round 14
// speedup vs baseline: 1.5854x; 1.5093x over previous
#include <cuda_runtime.h>
#include <cstdint>

#define TT 16384
#define DD 2048
#define EE 64
#define KSEL 8
#define BR 128
#define DC 32
#define NIT (DD / DC)       // 64 stages
#define XSTR 34             // X smem row stride (floats): 8B-aligned, bank-staggered
#define WSTR 68             // W smem d-row stride (floats): 16B-aligned
#define XBUF (BR * XSTR)    // 4352 floats
#define WBUF (DC * WSTR)    // 2176 floats
// dynamic smem = 2*XBUF + 2*WBUF = 13056 floats = 52224 B
// epilogue overlay L[128][68] = 8704 floats fits inside.

typedef unsigned long long ull;

__device__ float g_wt[DD * EE];   // transposed W: g_wt[d*64 + e] = W[e][d]
__device__ float g_cnt[EE];
__device__ float g_pn[EE];
__device__ int   g_done;

// ---------------------------------------------------------------------------
// Kernel A: zero accumulators + coalesced tiled transpose of W to d-major.
// 32 blocks x 256 threads, each block a 64e x 64d tile through padded smem.
// ---------------------------------------------------------------------------
__global__ void prep_kernel(const float* __restrict__ W) {
    __shared__ float tile[64][65];
    const int t = threadIdx.x;
    const int d0 = blockIdx.x * 64;

    if (blockIdx.x == 0) {
        if (t < EE)            g_cnt[t] = 0.f;
        else if (t < 2 * EE)   g_pn[t - EE] = 0.f;
        else if (t == 2 * EE)  g_done = 0;
    }

    #pragma unroll
    for (int j = 0; j < 16; j++) {
        int idx = j * 256 + t;            // 0..4095
        int e = idx >> 6, dl = idx & 63;  // coalesced read of W[e][d0+dl]
        tile[e][dl] = W[(size_t)e * DD + d0 + dl];
    }
    __syncthreads();
    #pragma unroll
    for (int j = 0; j < 16; j++) {
        int idx = j * 256 + t;
        int dl = idx >> 6, e = idx & 63;  // coalesced write of g_wt[d][e]
        g_wt[(size_t)(d0 + dl) * EE + e] = tile[e][dl];
    }
}

// packed fp32x2 FMA: each 32-bit lane is an independent sequential FFMA chain
__device__ __forceinline__ void ffma2(ull& c, ull a, ull b) {
    asm volatile("fma.rn.f32x2 %0, %1, %2, %0;" : "+l"(c) : "l"(a), "l"(b));
}
__device__ __forceinline__ ull dup32(uint32_t v) {
    ull r; asm("mov.b64 %0, {%1,%1};" : "=l"(r) : "r"(v)); return r;
}

extern __shared__ float smem[];

// ---------------------------------------------------------------------------
// Fused router: 128 blocks x 256 threads, 128 rows/block. (R7-proven body.)
// Warp wi owns experts 8wi..8wi+7 (W loads warp-uniform -> broadcast).
// Lane l owns rows {l, l+32, l+64, l+96}.
// acc[i][p] = packed (sum_e, sum_{e+1}) for expert pair p of row i —
// each lane is a plain sequential-d FFMA chain (exact, matches reference
// selection; proven in R5/R7). Last block folds the balance loss (ticket).
// ---------------------------------------------------------------------------
__global__ void __launch_bounds__(256, 1) router_kernel(
    const float* __restrict__ x,
    const float* __restrict__ bias,
    float* __restrict__ out)
{
    float* Xs  = smem;                 // [2][XBUF]
    float* Wsm = smem + 2 * XBUF;      // [2][WBUF]
    float* L   = smem;                 // epilogue overlay [128][68]

    __shared__ float bias_s[EE];
    __shared__ float cnt_s[EE];

    const int t    = threadIdx.x;
    const int wi   = t >> 5;
    const int lane = t & 31;
    const int r0   = blockIdx.x * BR;

    if (t < EE) { bias_s[t] = bias[t]; cnt_s[t] = 0.f; }

    // ---- X staging via 8B cp.async: thread t -> row t>>1, 16 floats (t&1 half)
    const int xrow = t >> 1;
    const int xh   = t & 1;
    const float* xsrc = x + (size_t)(r0 + xrow) * DD + xh * 16;
    const uint32_t xdst = (uint32_t)__cvta_generic_to_shared(
        Xs + xrow * XSTR + xh * 16);
    const uint32_t XBUF_B = XBUF * 4;

    // ---- W staging via 16B cp.async: 512 chunks/stage, 2 per thread
    const int d1 = t >> 4,        q1 = t & 15;
    const int d2 = (t + 256) >> 4;  // q same
    const float* wsrc1 = g_wt + (size_t)d1 * EE + 4 * q1;
    const float* wsrc2 = g_wt + (size_t)d2 * EE + 4 * q1;
    const uint32_t wdst1 = (uint32_t)__cvta_generic_to_shared(
        Wsm + d1 * WSTR + 4 * q1);
    const uint32_t wdst2 = (uint32_t)__cvta_generic_to_shared(
        Wsm + d2 * WSTR + 4 * q1);
    const uint32_t WBUF_B = WBUF * 4;

    ull acc[4][4];
    #pragma unroll
    for (int i = 0; i < 4; i++)
        #pragma unroll
        for (int p = 0; p < 4; p++) acc[i][p] = 0ULL;

    // ---- prologue: stage 0
    {
        #pragma unroll
        for (int k = 0; k < 8; k++)
            asm volatile("cp.async.ca.shared.global [%0], [%1], 8;"
                         :: "r"(xdst + 8 * k), "l"(xsrc + 2 * k));
        asm volatile("cp.async.cg.shared.global [%0], [%1], 16;" :: "r"(wdst1), "l"(wsrc1));
        asm volatile("cp.async.cg.shared.global [%0], [%1], 16;" :: "r"(wdst2), "l"(wsrc2));
        asm volatile("cp.async.commit_group;");
    }

    for (int s = 0; s < NIT; s++) {
        const int b = s & 1;

        if (s + 1 < NIT) {
            // prefetch stage s+1 into the other buffer
            const uint32_t xo = (b ^ 1) ? XBUF_B : 0u;
            const uint32_t wo = (b ^ 1) ? WBUF_B : 0u;
            const float* xs = xsrc + (size_t)(s + 1) * DC;
            const float* w1 = wsrc1 + (size_t)(s + 1) * DC * EE;
            const float* w2 = wsrc2 + (size_t)(s + 1) * DC * EE;
            #pragma unroll
            for (int k = 0; k < 8; k++)
                asm volatile("cp.async.ca.shared.global [%0], [%1], 8;"
                             :: "r"(xdst + xo + 8 * k), "l"(xs + 2 * k));
            asm volatile("cp.async.cg.shared.global [%0], [%1], 16;" :: "r"(wdst1 + wo), "l"(w1));
            asm volatile("cp.async.cg.shared.global [%0], [%1], 16;" :: "r"(wdst2 + wo), "l"(w2));
            asm volatile("cp.async.commit_group;");
            asm volatile("cp.async.wait_group 1;");
        } else {
            asm volatile("cp.async.wait_group 0;");
        }
        __syncthreads();

        // ---- compute stage s
        const float* xb = Xs + b * XBUF + lane * XSTR;
        const float* wb = Wsm + b * WBUF + 8 * wi;
        #pragma unroll 8
        for (int dl = 0; dl < DC; dl += 2) {
            // W for d=dl and d=dl+1: 4 expert-pairs each (warp-uniform)
            ulonglong2 wa0 = *(const ulonglong2*)(wb + dl * WSTR);
            ulonglong2 wa1 = *(const ulonglong2*)(wb + dl * WSTR + 4);
            ulonglong2 wb0 = *(const ulonglong2*)(wb + (dl + 1) * WSTR);
            ulonglong2 wb1 = *(const ulonglong2*)(wb + (dl + 1) * WSTR + 4);
            #pragma unroll
            for (int i = 0; i < 4; i++) {
                uint2 xv = *(const uint2*)(xb + i * (32 * XSTR) + dl);
                ull xa = dup32(xv.x);     // (x_d, x_d)
                ull xc = dup32(xv.y);     // (x_{d+1}, x_{d+1})
                ffma2(acc[i][0], xa, wa0.x);
                ffma2(acc[i][1], xa, wa0.y);
                ffma2(acc[i][2], xa, wa1.x);
                ffma2(acc[i][3], xa, wa1.y);
                ffma2(acc[i][0], xc, wb0.x);
                ffma2(acc[i][1], xc, wb0.y);
                ffma2(acc[i][2], xc, wb1.x);
                ffma2(acc[i][3], xc, wb1.y);
            }
        }
        __syncthreads();   // buffer b free before iter s+2 refills it
    }

    // ---- logits -> L[128][68]
    #pragma unroll
    for (int i = 0; i < 4; i++) {
        #pragma unroll
        for (int p = 0; p < 4; p++) {
            float2 f = *(float2*)&acc[i][p];
            const int rr = lane + 32 * i;
            const int ee = 8 * wi + 2 * p;
            L[rr * 68 + ee]     = f.x;
            L[rr * 68 + ee + 1] = f.y;
        }
    }
    __syncthreads();

    // ---- per-row: sigmoid, stable top-8 (strict > = lowest-index ties), gates
    if (t < BR) {
        float* Lr = L + t * 68;

        float ssum = 0.f;
        #pragma unroll
        for (int e = 0; e < EE; e++) {
            float sg = 1.f / (1.f + expf(-Lr[e]));
            Lr[e] = sg;
            ssum += sg;
        }

        ull mask = 0ULL;
        float gsum = 0.f;
        float gv[KSEL];
        int   gi[KSEL];
        #pragma unroll
        for (int k = 0; k < KSEL; k++) {
            float best = -3.4e38f;
            int bi = 0;
            for (int e = 0; e < EE; e++) {
                if ((mask >> e) & 1ULL) continue;
                float v = Lr[e] + bias_s[e];
                if (v > best) { best = v; bi = e; }
            }
            mask |= (1ULL << bi);
            gi[k] = bi;
            float a = Lr[bi];
            gv[k] = a;
            gsum += a;
            atomicAdd(&cnt_s[bi], 1.f);
        }

        const float inv = 1.f / (gsum + 1e-9f);
        const size_t rgl = (size_t)r0 + t;
        #pragma unroll
        for (int k = 0; k < KSEL; k++) {
            out[rgl * KSEL + k]                     = gv[k] * inv;
            out[(size_t)TT * KSEL + rgl * KSEL + k] = (float)gi[k];
        }

        const float pinv = 1.f / (ssum + 1e-9f);
        #pragma unroll
        for (int e = 0; e < EE; e++) Lr[e] *= pinv;   // affinity_norm for P
    }
    __syncthreads();

    // ---- per-expert partial sums of affinity_norm -> global atomics
    {
        const int e   = t & 63;
        const int seg = t >> 6;        // 4 segments x 32 rows
        float s = 0.f;
        #pragma unroll
        for (int r = seg * 32; r < seg * 32 + 32; r++) s += L[r * 68 + e];
        atomicAdd(&g_pn[e], s);
    }
    if (t < EE) atomicAdd(&g_cnt[t], cnt_s[t]);
    __syncthreads();

    // ---- last-block ticket: fold the balance loss (replaces finalize kernel)
    if (t == 0) {
        __threadfence();
        if (atomicAdd(&g_done, 1) == gridDim.x - 1) {
            float s = 0.f;
            for (int i = 0; i < EE; i++) {
                float c = atomicAdd(&g_cnt[i], 0.f);   // L2-coherent read
                float p = atomicAdd(&g_pn[i], 0.f);
                s += c * p;
            }
            double loss = (double)s * 1e-4 * 64.0 / (8.0 * 16384.0) / 16384.0;
            out[(size_t)2 * TT * KSEL] = (float)loss;
        }
    }
}

// ---------------------------------------------------------------------------
extern "C" void kernel_launch(void* const* d_in, const int* in_sizes, int n_in,
                              void* d_out, int out_size) {
    const float* x    = (const float*)d_in[0];
    const float* W    = (const float*)d_in[1];
    const float* bias = (const float*)d_in[2];
    float* out = (float*)d_out;

    static bool attr_done = false;
    if (!attr_done) {
        cudaFuncSetAttribute(router_kernel,
                             cudaFuncAttributeMaxDynamicSharedMemorySize, 53248);
        attr_done = true;
    }

    prep_kernel<<<32, 256>>>(W);
    router_kernel<<<TT / BR, 256, 52224>>>(x, bias, out);
}